// round 13
// baseline (speedup 1.0000x reference)
#include <cuda_runtime.h>

// LinearChainCRF: mean(logZ - gold) over B=16384 sequences of T=512, N_TAGS=4.
//
// Algebra: the reference's logsumexp is over the LAST axis (j); alpha[i] is
// constant in j, so the "scan" is purely additive:
//   alpha_T[i] = em[0,i] + sum_{t>=1} mask_t * log(s_i(t)),
//   s_i(t)     = sum_j exp(trans[i,j]) * exp(em[t,j])   (|e| <~ 6 -> no norm)
//   logZ       = logsumexp_i(alpha_T[i]);  result = mean(logZ - gold).
//
// R13: per-thread mapping t = i*128 + lane*4 + u (4 consecutive timesteps)
// so tags and mask load as int4/uchar4 vectors: 48 scalar 4B LDGs/thread
// become ~8 vector loads + <=4 L1-hit ptag loads. R12 was issue-limited
// (issue 50%, DRAM 51%, occ 87%); this cuts ~25% of the instruction stream.
// Keeps __launch_bounds__(256,8) (32 regs -> 8 blocks/SM, the R12 win).
// Fused deterministic reduction: Q32.32 integer bucket atomics + ticket.

#define T_LEN 512
#define WARPS_PER_BLOCK 8
#define NTHREADS (32 * WARPS_PER_BLOCK)
#define NBUCKETS 64
#define FIXED_SCALE 4294967296.0   // 2^32

__device__ unsigned long long g_buckets[NBUCKETS];  // zero at load; self-reset
__device__ unsigned int g_ticket;                   // used modulo grid size

// Branch-free specialized warp worker. Returns logZ-gold (valid on lane 0).
// No block-level synchronization inside (safe under divergent dispatch).
template <bool IS64, int MW>
__device__ __forceinline__ float warp_crf(int base, int lane,
                                          const float4* __restrict__ em4,
                                          const void* __restrict__ tags_raw,
                                          const void* __restrict__ mask_raw,
                                          const float* trans_s,
                                          const float eT[16])
{
    const long long* tg64 = (const long long*)tags_raw;
    const int* tg32 = (const int*)tags_raw;
    const unsigned full = 0xffffffffu;

    float c0 = 0.f, c1 = 0.f, c2 = 0.f, c3 = 0.f, gold = 0.f;
    float a0 = 0.f, a1 = 0.f, a2 = 0.f, a3 = 0.f;   // alpha0 (lane 0 only)

    #pragma unroll
    for (int i = 0; i < 4; ++i) {
        const int t0 = i * 128 + lane * 4;
        const int idx0 = base + t0;

        // --- vector tag load: 4 consecutive tags ---
        int tg[4];
        if (!IS64) {
            const int4 tv = ((const int4*)tg32)[idx0 >> 2];
            tg[0] = tv.x; tg[1] = tv.y; tg[2] = tv.z; tg[3] = tv.w;
        } else {
            const longlong2 ta = ((const longlong2*)tg64)[idx0 >> 1];
            const longlong2 tb = ((const longlong2*)tg64)[(idx0 >> 1) + 1];
            tg[0] = (int)ta.x; tg[1] = (int)ta.y;
            tg[2] = (int)tb.x; tg[3] = (int)tb.y;
        }
        // --- vector mask load: 4 consecutive mask values ---
        float mk[4];
        if (MW == 1) {
            const uchar4 mv = ((const uchar4*)mask_raw)[idx0 >> 2];
            mk[0] = mv.x ? 1.f : 0.f; mk[1] = mv.y ? 1.f : 0.f;
            mk[2] = mv.z ? 1.f : 0.f; mk[3] = mv.w ? 1.f : 0.f;
        } else if (MW == 4) {
            const int4 mv = ((const int4*)mask_raw)[idx0 >> 2];
            mk[0] = mv.x ? 1.f : 0.f; mk[1] = mv.y ? 1.f : 0.f;
            mk[2] = mv.z ? 1.f : 0.f; mk[3] = mv.w ? 1.f : 0.f;
        } else {
            const longlong2 ma = ((const longlong2*)mask_raw)[idx0 >> 1];
            const longlong2 mb = ((const longlong2*)mask_raw)[(idx0 >> 1) + 1];
            mk[0] = ma.x ? 1.f : 0.f; mk[1] = ma.y ? 1.f : 0.f;
            mk[2] = mb.x ? 1.f : 0.f; mk[3] = mb.y ? 1.f : 0.f;
        }
        // --- ptag for u=0: previous timestep's tag (L1 hit; skip at t=0) ---
        int ptag0 = 0;
        if (t0 > 0)
            ptag0 = IS64 ? (int)tg64[idx0 - 1] : tg32[idx0 - 1];

        float pr0 = 1.f, pr1 = 1.f, pr2 = 1.f, pr3 = 1.f;
        #pragma unroll
        for (int u = 0; u < 4; ++u) {
            const float4 e = em4[idx0 + u];
            const int tag = tg[u];
            const int ptag = (u == 0) ? ptag0 : tg[u - 1];
            const float m = mk[u];

            const float etag = (tag == 0) ? e.x : (tag == 1) ? e.y
                             : (tag == 2) ? e.z : e.w;

            if (i == 0 && u == 0 && lane == 0) {
                // t == 0: alpha0 row; no transition term.
                gold += m * etag;
                a0 = e.x; a1 = e.y; a2 = e.z; a3 = e.w;
            } else {
                gold += m * (etag + trans_s[ptag * 4 + tag]);
                const float q0 = __expf(e.x);
                const float q1 = __expf(e.y);
                const float q2 = __expf(e.z);
                const float q3 = __expf(e.w);
                float s0 = eT[0]  * q0 + eT[1]  * q1 + eT[2]  * q2 + eT[3]  * q3;
                float s1 = eT[4]  * q0 + eT[5]  * q1 + eT[6]  * q2 + eT[7]  * q3;
                float s2 = eT[8]  * q0 + eT[9]  * q1 + eT[10] * q2 + eT[11] * q3;
                float s3 = eT[12] * q0 + eT[13] * q1 + eT[14] * q2 + eT[15] * q3;
                pr0 *= (m != 0.f) ? s0 : 1.0f;
                pr1 *= (m != 0.f) ? s1 : 1.0f;
                pr2 *= (m != 0.f) ? s2 : 1.0f;
                pr3 *= (m != 0.f) ? s3 : 1.0f;
            }
        }
        c0 += __logf(pr0);
        c1 += __logf(pr1);
        c2 += __logf(pr2);
        c3 += __logf(pr3);
    }

    // warp-wide sums of {c0,c1,c2,c3,gold}
    float v[5] = {c0, c1, c2, c3, gold};
    #pragma unroll
    for (int k = 0; k < 5; ++k) {
        float x = v[k];
        x += __shfl_xor_sync(full, x, 16);
        x += __shfl_xor_sync(full, x, 8);
        x += __shfl_xor_sync(full, x, 4);
        x += __shfl_xor_sync(full, x, 2);
        x += __shfl_xor_sync(full, x, 1);
        v[k] = x;
    }

    const float f0 = a0 + v[0];
    const float f1 = a1 + v[1];
    const float f2 = a2 + v[2];
    const float f3 = a3 + v[3];
    const float mx = fmaxf(fmaxf(f0, f1), fmaxf(f2, f3));
    const float logZ = mx + __logf(__expf(f0 - mx) + __expf(f1 - mx) +
                                   __expf(f2 - mx) + __expf(f3 - mx));
    return logZ - v[4];
}

__global__ __launch_bounds__(NTHREADS, 8)
void crf_warp_kernel(const float* __restrict__ emissions,
                     const void* __restrict__ tags_raw,
                     const void* __restrict__ mask_raw,
                     const float* __restrict__ transitions,
                     float* __restrict__ out, int B)
{
    __shared__ float trans_s[16];
    __shared__ float expT_s[16];
    __shared__ int s_last;

    const int lane = threadIdx.x & 31;
    const int warp = threadIdx.x >> 5;
    const int b = blockIdx.x * WARPS_PER_BLOCK + warp;
    const unsigned full = 0xffffffffu;

    if (threadIdx.x < 16) {
        float tv = transitions[threadIdx.x];
        trans_s[threadIdx.x] = tv;
        expT_s[threadIdx.x] = __expf(tv);
    }
    __syncthreads();

    // ---- warp-parallel dtype probes (first words; L2-resident after block 0) --
    const int* tags32p = (const int*)tags_raw;
    const unsigned int* mask32p = (const unsigned int*)mask_raw;
    // tags int64 <=> odd int32 words all zero (tags in [0,4); P(miss)~(1/4)^32)
    const int tag_is64 = (__ballot_sync(full, tags32p[2 * lane + 1] != 0) == 0u);
    // mask: u8 -> hi bytes of words set; i32 -> odd words nonzero; i64 -> neither
    const unsigned int hi = __ballot_sync(full, (mask32p[lane] & 0xFFFFFF00u) != 0u);
    const unsigned int od = __ballot_sync(full, mask32p[2 * lane + 1] != 0u);
    const int mask_w = hi ? 1 : (od ? 4 : 8);

    float eT[16];
    #pragma unroll
    for (int i = 0; i < 16; ++i) eT[i] = expT_s[i];

    const int base = b * T_LEN;                      // <= 8.4M: 32-bit safe
    const float4* em4 = (const float4*)emissions;

    // One-time uniform dispatch to the branch-free specialized loop.
    float r;
    if (tag_is64) {
        if (mask_w == 1)
            r = warp_crf<true, 1>(base, lane, em4, tags_raw, mask_raw, trans_s, eT);
        else if (mask_w == 4)
            r = warp_crf<true, 4>(base, lane, em4, tags_raw, mask_raw, trans_s, eT);
        else
            r = warp_crf<true, 8>(base, lane, em4, tags_raw, mask_raw, trans_s, eT);
    } else {
        if (mask_w == 1)
            r = warp_crf<false, 1>(base, lane, em4, tags_raw, mask_raw, trans_s, eT);
        else if (mask_w == 4)
            r = warp_crf<false, 4>(base, lane, em4, tags_raw, mask_raw, trans_s, eT);
        else
            r = warp_crf<false, 8>(base, lane, em4, tags_raw, mask_raw, trans_s, eT);
    }

    if (lane == 0) {
        // Deterministic fixed-point accumulation (integer adds associative).
        long long q = llrint((double)r * FIXED_SCALE);
        atomicAdd(&g_buckets[b & (NBUCKETS - 1)], (unsigned long long)q);
    }

    // ---- ticket: last block folds the buckets ----
    __syncthreads();          // all warps' bucket atomics issued
    __threadfence();
    if (threadIdx.x == 0) {
        unsigned int old = atomicAdd(&g_ticket, 1u);
        // 2^32 % gridDim.x == 0 (grid = 2048): replay-safe without a reset.
        s_last = ((old % gridDim.x) == gridDim.x - 1u);
    }
    __syncthreads();

    if (s_last && threadIdx.x == 0) {
        long long total = 0;
        #pragma unroll
        for (int i = 0; i < NBUCKETS; ++i) total += (long long)g_buckets[i];
        out[0] = (float)(((double)total / FIXED_SCALE) / (double)B);
        #pragma unroll
        for (int i = 0; i < NBUCKETS; ++i) g_buckets[i] = 0ULL;  // next replay
    }
}

extern "C" void kernel_launch(void* const* d_in, const int* in_sizes, int n_in,
                              void* d_out, int out_size)
{
    const float* emissions   = (const float*)d_in[0];
    const void*  tags        = (const void*)d_in[1];
    const void*  mask        = (const void*)d_in[2];
    const float* transitions = (const float*)d_in[3];

    const int B = in_sizes[0] / (T_LEN * 4);   // emissions: B*T*4 floats

    crf_warp_kernel<<<B / WARPS_PER_BLOCK, NTHREADS>>>(
        emissions, tags, mask, transitions, (float*)d_out, B);
}

// round 15
// speedup vs baseline: 1.0075x; 1.0075x over previous
#include <cuda_runtime.h>

// LinearChainCRF: mean(logZ - gold) over B=16384 sequences of T=512, N_TAGS=4.
//
// Algebra: the reference's logsumexp is over the LAST axis (j); alpha[i] is
// constant in j, so the "scan" is purely additive:
//   alpha_T[i] = em[0,i] + sum_{t>=1} mask_t * log(s_i(t)),
//   s_i(t)     = sum_j exp(trans[i,j]) * exp(em[t,j])   (|e| <~ 6 -> no norm)
//   logZ       = logsumexp_i(alpha_T[i]);  result = mean(logZ - gold).
//
// R15 = R14 resubmitted (container infra failure, kernel never ran):
// R12 skeleton (stride-32 warp-per-sequence, 16 t/thread, branch-free
// template dispatch, __launch_bounds__(256,8), fused Q32.32 reduction)
// + packed f32x2 math: 16 FFMA -> 8 fma.rn.f32x2 on (s0,s1)/(s2,s3) pairs,
//   4 FMUL+4 SEL -> 2 mul.rn.f32x2 + 2 sel (ptxas never emits FFMA2 itself)
// + log grouping 4 -> 8 (8-product range [6e-22, 9e24], fp32-safe):
//   16 logf/thread -> 8.
// R13's 4-consecutive layout stays REVERTED (it 4x'd emission L1 wavefronts).

#define T_LEN 512
#define WARPS_PER_BLOCK 8
#define NTHREADS (32 * WARPS_PER_BLOCK)
#define NBUCKETS 64
#define FIXED_SCALE 4294967296.0   // 2^32
#define ONE2 0x3F8000003F800000ULL // packed (1.0f, 1.0f)

__device__ unsigned long long g_buckets[NBUCKETS];  // zero at load; self-reset
__device__ unsigned int g_ticket;                   // used modulo grid size

// Branch-free specialized warp worker. Returns logZ-gold (valid on lane 0).
// eA[j] = pack(expT[0*4+j], expT[1*4+j]); eB[j] = pack(expT[2*4+j], expT[3*4+j]).
template <bool IS64, int MW>
__device__ __forceinline__ float warp_crf(int base, int lane,
                                          const float4* __restrict__ em4,
                                          const void* __restrict__ tags_raw,
                                          const void* __restrict__ mask_raw,
                                          const float* trans_s,
                                          const unsigned long long eA[4],
                                          const unsigned long long eB[4])
{
    const long long* tg64 = (const long long*)tags_raw;
    const int* tg32 = (const int*)tags_raw;
    const unsigned full = 0xffffffffu;

    float c0 = 0.f, c1 = 0.f, c2 = 0.f, c3 = 0.f, gold = 0.f;
    float a0 = 0.f, a1 = 0.f, a2 = 0.f, a3 = 0.f;   // alpha0 (lane 0 only)

    #pragma unroll
    for (int chunk = 0; chunk < 2; ++chunk) {
        unsigned long long pr01 = ONE2, pr23 = ONE2;
        #pragma unroll
        for (int u = 0; u < 8; ++u) {
            const int t = (chunk * 8 + u) * 32 + lane;
            const int idx = base + t;

            const float4 e = em4[idx];

            int tag, ptag = 0;
            if (IS64) {
                tag = (int)tg64[idx];
                if (t > 0) ptag = (int)tg64[idx - 1];
            } else {
                tag = tg32[idx];
                if (t > 0) ptag = tg32[idx - 1];
            }
            float m;
            if (MW == 1)      m = ((const unsigned char*)mask_raw)[idx] ? 1.0f : 0.0f;
            else if (MW == 4) m = ((const int*)mask_raw)[idx] ? 1.0f : 0.0f;
            else              m = ((const long long*)mask_raw)[idx] ? 1.0f : 0.0f;

            const float etag = (tag == 0) ? e.x : (tag == 1) ? e.y
                             : (tag == 2) ? e.z : e.w;

            if (t == 0) {
                gold += m * etag;
                a0 = e.x; a1 = e.y; a2 = e.z; a3 = e.w;
            } else {
                gold += m * (etag + trans_s[ptag * 4 + tag]);
                const float q[4] = {__expf(e.x), __expf(e.y),
                                    __expf(e.z), __expf(e.w)};
                unsigned long long acc01 = 0ULL, acc23 = 0ULL;
                #pragma unroll
                for (int j = 0; j < 4; ++j) {
                    unsigned long long qq;
                    asm("mov.b64 %0, {%1, %1};"
                        : "=l"(qq) : "r"(__float_as_uint(q[j])));
                    asm("fma.rn.f32x2 %0, %1, %2, %3;"
                        : "=l"(acc01) : "l"(eA[j]), "l"(qq), "l"(acc01));
                    asm("fma.rn.f32x2 %0, %1, %2, %3;"
                        : "=l"(acc23) : "l"(eB[j]), "l"(qq), "l"(acc23));
                }
                const unsigned long long t01 = (m != 0.f) ? acc01 : ONE2;
                const unsigned long long t23 = (m != 0.f) ? acc23 : ONE2;
                asm("mul.rn.f32x2 %0, %1, %2;"
                    : "=l"(pr01) : "l"(pr01), "l"(t01));
                asm("mul.rn.f32x2 %0, %1, %2;"
                    : "=l"(pr23) : "l"(pr23), "l"(t23));
            }
        }
        unsigned int lo, hi;
        asm("mov.b64 {%0, %1}, %2;" : "=r"(lo), "=r"(hi) : "l"(pr01));
        c0 += __logf(__uint_as_float(lo));
        c1 += __logf(__uint_as_float(hi));
        asm("mov.b64 {%0, %1}, %2;" : "=r"(lo), "=r"(hi) : "l"(pr23));
        c2 += __logf(__uint_as_float(lo));
        c3 += __logf(__uint_as_float(hi));
    }

    // warp-wide sums of {c0,c1,c2,c3,gold}
    float v[5] = {c0, c1, c2, c3, gold};
    #pragma unroll
    for (int k = 0; k < 5; ++k) {
        float x = v[k];
        x += __shfl_xor_sync(full, x, 16);
        x += __shfl_xor_sync(full, x, 8);
        x += __shfl_xor_sync(full, x, 4);
        x += __shfl_xor_sync(full, x, 2);
        x += __shfl_xor_sync(full, x, 1);
        v[k] = x;
    }

    const float f0 = a0 + v[0];
    const float f1 = a1 + v[1];
    const float f2 = a2 + v[2];
    const float f3 = a3 + v[3];
    const float mx = fmaxf(fmaxf(f0, f1), fmaxf(f2, f3));
    const float logZ = mx + __logf(__expf(f0 - mx) + __expf(f1 - mx) +
                                   __expf(f2 - mx) + __expf(f3 - mx));
    return logZ - v[4];
}

__global__ __launch_bounds__(NTHREADS, 8)
void crf_warp_kernel(const float* __restrict__ emissions,
                     const void* __restrict__ tags_raw,
                     const void* __restrict__ mask_raw,
                     const float* __restrict__ transitions,
                     float* __restrict__ out, int B)
{
    __shared__ float trans_s[16];
    __shared__ float expT_s[16];
    __shared__ int s_last;

    const int lane = threadIdx.x & 31;
    const int warp = threadIdx.x >> 5;
    const int b = blockIdx.x * WARPS_PER_BLOCK + warp;
    const unsigned full = 0xffffffffu;

    if (threadIdx.x < 16) {
        float tv = transitions[threadIdx.x];
        trans_s[threadIdx.x] = tv;
        expT_s[threadIdx.x] = __expf(tv);
    }
    __syncthreads();

    // ---- warp-parallel dtype probes (first words; L2-resident after block 0) --
    const int* tags32p = (const int*)tags_raw;
    const unsigned int* mask32p = (const unsigned int*)mask_raw;
    // tags int64 <=> odd int32 words all zero (tags in [0,4); P(miss)~(1/4)^32)
    const int tag_is64 = (__ballot_sync(full, tags32p[2 * lane + 1] != 0) == 0u);
    // mask: u8 -> hi bytes of words set; i32 -> odd words nonzero; i64 -> neither
    const unsigned int hi = __ballot_sync(full, (mask32p[lane] & 0xFFFFFF00u) != 0u);
    const unsigned int od = __ballot_sync(full, mask32p[2 * lane + 1] != 0u);
    const int mask_w = hi ? 1 : (od ? 4 : 8);

    // Packed expT coefficient pairs: eA -> (s0,s1), eB -> (s2,s3).
    unsigned long long eA[4], eB[4];
    #pragma unroll
    for (int j = 0; j < 4; ++j) {
        eA[j] = ((unsigned long long)__float_as_uint(expT_s[4 + j]) << 32)
              | __float_as_uint(expT_s[j]);
        eB[j] = ((unsigned long long)__float_as_uint(expT_s[12 + j]) << 32)
              | __float_as_uint(expT_s[8 + j]);
    }

    const int base = b * T_LEN;                      // <= 8.4M: 32-bit safe
    const float4* em4 = (const float4*)emissions;

    // One-time uniform dispatch to the branch-free specialized loop.
    float r;
    if (tag_is64) {
        if (mask_w == 1)
            r = warp_crf<true, 1>(base, lane, em4, tags_raw, mask_raw, trans_s, eA, eB);
        else if (mask_w == 4)
            r = warp_crf<true, 4>(base, lane, em4, tags_raw, mask_raw, trans_s, eA, eB);
        else
            r = warp_crf<true, 8>(base, lane, em4, tags_raw, mask_raw, trans_s, eA, eB);
    } else {
        if (mask_w == 1)
            r = warp_crf<false, 1>(base, lane, em4, tags_raw, mask_raw, trans_s, eA, eB);
        else if (mask_w == 4)
            r = warp_crf<false, 4>(base, lane, em4, tags_raw, mask_raw, trans_s, eA, eB);
        else
            r = warp_crf<false, 8>(base, lane, em4, tags_raw, mask_raw, trans_s, eA, eB);
    }

    if (lane == 0) {
        // Deterministic fixed-point accumulation (integer adds associative).
        long long q = llrint((double)r * FIXED_SCALE);
        atomicAdd(&g_buckets[b & (NBUCKETS - 1)], (unsigned long long)q);
    }

    // ---- ticket: last block folds the buckets ----
    __syncthreads();          // all warps' bucket atomics issued
    __threadfence();
    if (threadIdx.x == 0) {
        unsigned int old = atomicAdd(&g_ticket, 1u);
        // 2^32 % gridDim.x == 0 (grid = 2048): replay-safe without a reset.
        s_last = ((old % gridDim.x) == gridDim.x - 1u);
    }
    __syncthreads();

    if (s_last && threadIdx.x == 0) {
        long long total = 0;
        #pragma unroll
        for (int i = 0; i < NBUCKETS; ++i) total += (long long)g_buckets[i];
        out[0] = (float)(((double)total / FIXED_SCALE) / (double)B);
        #pragma unroll
        for (int i = 0; i < NBUCKETS; ++i) g_buckets[i] = 0ULL;  // next replay
    }
}

extern "C" void kernel_launch(void* const* d_in, const int* in_sizes, int n_in,
                              void* d_out, int out_size)
{
    const float* emissions   = (const float*)d_in[0];
    const void*  tags        = (const void*)d_in[1];
    const void*  mask        = (const void*)d_in[2];
    const float* transitions = (const float*)d_in[3];

    const int B = in_sizes[0] / (T_LEN * 4);   // emissions: B*T*4 floats

    crf_warp_kernel<<<B / WARPS_PER_BLOCK, NTHREADS>>>(
        emissions, tags, mask, transitions, (float*)d_out, B);
}